// round 1
// baseline (speedup 1.0000x reference)
#include <cuda_runtime.h>
#include <cuda_bf16.h>

// VQQuantizer: z [16,1024,512] f32, codebook [2048,64] f32.
// N = 131072 query vectors (D=64), K = 2048 codes.
// out = [codes (N*64 f32) | indices (N f32) | commit_loss (1 f32)]
//
// score_k = z . c_k - 0.5*||c_k||^2 ; argmax score == argmin dist.
// Full fp32 via packed f32x2 FFMA (2 MACs/lane/instr).

#define MT 128          // queries per CTA
#define NT 128          // codes per tile
#define DK 64           // reduction dim
#define PITCH 132       // smem row pitch (floats), 16B-aligned, conflict-mitigating

__device__ float  g_cn2[4096];     // 0.5*||c_k||^2
__device__ double g_accum;         // commit-loss accumulator

// ---- packed f32x2 helpers ----
__device__ __forceinline__ unsigned long long pk(float x) {
    unsigned long long r;
    asm("mov.b64 %0, {%1, %1};" : "=l"(r) : "f"(x));
    return r;
}
__device__ __forceinline__ void ffma2(unsigned long long& d,
                                      unsigned long long a,
                                      unsigned long long b) {
    asm("fma.rn.f32x2 %0, %1, %2, %0;" : "+l"(d) : "l"(a), "l"(b));
}
__device__ __forceinline__ void upk(unsigned long long v, float& lo, float& hi) {
    asm("mov.b64 {%0, %1}, %2;" : "=f"(lo), "=f"(hi) : "l"(v));
}

// ---- init: codebook half-norms + zero loss accumulator ----
__global__ void vq_init_kernel(const float* __restrict__ cb, int K) {
    int k = blockIdx.x * blockDim.x + threadIdx.x;
    if (k == 0 && blockIdx.x == 0) g_accum = 0.0;
    if (k < K) {
        const float4* r = reinterpret_cast<const float4*>(cb + (size_t)k * DK);
        float s = 0.f;
        #pragma unroll
        for (int u = 0; u < DK / 4; u++) {
            float4 v = r[u];
            s += v.x * v.x + v.y * v.y + v.z * v.z + v.w * v.w;
        }
        g_cn2[k] = 0.5f * s;
    }
}

// ---- finalize: write mean commit loss ----
__global__ void vq_finish_kernel(float* __restrict__ out, int NQ) {
    out[(size_t)NQ * (DK + 1)] = (float)(g_accum / ((double)NQ * (double)DK));
}

// ---- main: GEMM + fused argmax + codes/loss epilogue ----
__global__ __launch_bounds__(256, 2)
void vq_main_kernel(const float* __restrict__ z,
                    const float* __restrict__ cb,
                    float* __restrict__ out,
                    int NQ, int K) {
    extern __shared__ float smem[];
    float* zs   = smem;                      // [DK][PITCH]  (transposed z tile)
    float* cs   = smem + DK * PITCH;         // [DK][PITCH]  (transposed code tile)
    float* cn2s = smem + 2 * DK * PITCH;     // [NT]
    int*   bq   = (int*)(cn2s + NT);         // [MT] best index per query
    float* wred = (float*)(bq + MT);         // [8] warp loss sums

    const int tid = threadIdx.x;
    const int tx  = tid & 15;    // code direction
    const int ty  = tid >> 4;    // query direction
    const int q0  = blockIdx.x * MT;

    // --- load z tile [MT x DK] transposed into zs[d][q] ---
    {
        const float4* zg = reinterpret_cast<const float4*>(z + (size_t)q0 * DK);
        #pragma unroll
        for (int u = 0; u < (MT * DK / 4) / 256; u++) {
            int i4  = tid + 256 * u;
            int row = i4 >> 4;          // query row
            int d4  = i4 & 15;          // float4 index along d
            float4 v = zg[row * 16 + d4];
            float* p = zs + (d4 * 4) * PITCH + row;
            p[0 * PITCH] = v.x; p[1 * PITCH] = v.y;
            p[2 * PITCH] = v.z; p[3 * PITCH] = v.w;
        }
    }

    float best[8];
    int   bix[8];
    #pragma unroll
    for (int i = 0; i < 8; i++) { best[i] = -3.4e38f; bix[i] = 0; }

    for (int kt = 0; kt < K; kt += NT) {
        __syncthreads();   // protect cs/cn2s from previous tile's readers
        // --- load code tile [NT x DK] transposed into cs[d][k] ---
        {
            const float4* cg = reinterpret_cast<const float4*>(cb + (size_t)kt * DK);
            #pragma unroll
            for (int u = 0; u < (NT * DK / 4) / 256; u++) {
                int i4  = tid + 256 * u;
                int row = i4 >> 4;
                int d4  = i4 & 15;
                float4 v = cg[row * 16 + d4];
                float* p = cs + (d4 * 4) * PITCH + row;
                p[0 * PITCH] = v.x; p[1 * PITCH] = v.y;
                p[2 * PITCH] = v.z; p[3 * PITCH] = v.w;
            }
        }
        if (tid < NT) cn2s[tid] = g_cn2[kt + tid];
        __syncthreads();

        // --- compute: acc[i][u] = packed dot for rows ty*8+i, codes tx*8+{2u,2u+1} ---
        unsigned long long acc[8][4];
        #pragma unroll
        for (int i = 0; i < 8; i++)
            #pragma unroll
            for (int u = 0; u < 4; u++) acc[i][u] = 0ull;

        #pragma unroll 4
        for (int d = 0; d < DK; ++d) {
            const float* zr = zs + d * PITCH + (ty << 3);
            float4 a0 = *reinterpret_cast<const float4*>(zr);
            float4 a1 = *reinterpret_cast<const float4*>(zr + 4);
            const float* cr = cs + d * PITCH + (tx << 3);
            ulonglong2 b0 = *reinterpret_cast<const ulonglong2*>(cr);
            ulonglong2 b1 = *reinterpret_cast<const ulonglong2*>(cr + 4);
            float av[8] = {a0.x, a0.y, a0.z, a0.w, a1.x, a1.y, a1.z, a1.w};
            #pragma unroll
            for (int i = 0; i < 8; i++) {
                unsigned long long ap = pk(av[i]);
                ffma2(acc[i][0], ap, b0.x);
                ffma2(acc[i][1], ap, b0.y);
                ffma2(acc[i][2], ap, b1.x);
                ffma2(acc[i][3], ap, b1.y);
            }
        }

        // --- argmax update ---
        const int cbase = kt + (tx << 3);
        float cn[8];
        #pragma unroll
        for (int j = 0; j < 8; j++) cn[j] = cn2s[(tx << 3) + j];
        #pragma unroll
        for (int i = 0; i < 8; i++) {
            #pragma unroll
            for (int u = 0; u < 4; u++) {
                float s0, s1;
                upk(acc[i][u], s0, s1);
                s0 -= cn[2 * u];
                s1 -= cn[2 * u + 1];
                if (s0 > best[i]) { best[i] = s0; bix[i] = cbase + 2 * u; }
                if (s1 > best[i]) { best[i] = s1; bix[i] = cbase + 2 * u + 1; }
            }
        }
    }

    // --- cross-lane arg-reduction over the 16 tx lanes (tie -> lowest index) ---
    #pragma unroll
    for (int i = 0; i < 8; i++) {
        float s = best[i];
        int   ix = bix[i];
        #pragma unroll
        for (int off = 8; off >= 1; off >>= 1) {
            float s2 = __shfl_down_sync(0xffffffffu, s, off, 16);
            int   i2 = __shfl_down_sync(0xffffffffu, ix, off, 16);
            if (s2 > s || (s2 == s && i2 < ix)) { s = s2; ix = i2; }
        }
        if (tx == 0) bq[(ty << 3) + i] = ix;
    }
    __syncthreads();

    // --- indices output (as float) ---
    if (tid < MT) {
        out[(size_t)NQ * DK + q0 + tid] = (float)bq[tid];
    }

    // --- codes output + commit loss (each thread: half a query row = 32 floats) ---
    float lsum = 0.f;
    {
        int q = tid >> 1, h = tid & 1;
        const float4* crow = reinterpret_cast<const float4*>(cb + (size_t)bq[q] * DK) + h * 8;
        const float4* zrow = reinterpret_cast<const float4*>(z + (size_t)(q0 + q) * DK) + h * 8;
        float4*       orow = reinterpret_cast<float4*>(out + (size_t)(q0 + q) * DK) + h * 8;
        #pragma unroll
        for (int u = 0; u < 8; u++) {
            float4 c = crow[u];
            float4 zz = zrow[u];
            orow[u] = c;
            float dx = c.x - zz.x, dy = c.y - zz.y, dz = c.z - zz.z, dw = c.w - zz.w;
            lsum += dx * dx + dy * dy + dz * dz + dw * dw;
        }
    }
    // block reduce loss -> one double atomic per CTA
    #pragma unroll
    for (int off = 16; off >= 1; off >>= 1)
        lsum += __shfl_down_sync(0xffffffffu, lsum, off, 32);
    if ((tid & 31) == 0) wred[tid >> 5] = lsum;
    __syncthreads();
    if (tid == 0) {
        float t = 0.f;
        #pragma unroll
        for (int w = 0; w < 8; w++) t += wred[w];
        atomicAdd(&g_accum, (double)t);
    }
}

extern "C" void kernel_launch(void* const* d_in, const int* in_sizes, int n_in,
                              void* d_out, int out_size) {
    (void)n_in; (void)out_size;
    const float* z  = (const float*)d_in[0];
    const float* cb = (const float*)d_in[1];
    float* out = (float*)d_out;

    const int NQ = in_sizes[0] / DK;   // 131072
    const int K  = in_sizes[1] / DK;   // 2048

    static int smem_set = 0;
    const int smem_bytes = (2 * DK * PITCH + NT + MT + 8) * 4;
    if (!smem_set) {
        cudaFuncSetAttribute(vq_main_kernel,
                             cudaFuncAttributeMaxDynamicSharedMemorySize,
                             smem_bytes);
        smem_set = 1;
    }

    vq_init_kernel<<<(K + 127) / 128, 128>>>(cb, K);
    vq_main_kernel<<<NQ / MT, 256, smem_bytes>>>(z, cb, out, NQ, K);
    vq_finish_kernel<<<1, 1>>>(out, NQ);
}

// round 3
// speedup vs baseline: 1.5574x; 1.5574x over previous
#include <cuda_runtime.h>
#include <cstdint>

// VQQuantizer via mma.sync tf32 3-MMA fp32 emulation (plain sm_103 target).
// z [131072 x 64] f32, codebook [2048 x 64] f32.
// out = [codes (N*64) | indices (N) | loss (1)] f32.
// score = z.c - 0.5||c||^2 ; argmax score == argmin dist.

#define DK      64
#define MT      128          // queries per CTA
#define NT      64           // codes per tile
#define KCODES  2048
#define TILES   (KCODES / NT)
#define THREADS 256

// packed codebook fragments: per tile [split(2)][chunk=ks*8+nt (64)][lane(32)][2]
__device__ __align__(16) float g_cbp[KCODES * DK * 2];
__device__ __align__(16) float g_cn2[KCODES];
__device__ double g_accum;

// ---------------- helpers ----------------
__device__ __forceinline__ float tf32_rna(float x) {
    uint32_t r;
    asm("cvt.rna.tf32.f32 %0, %1;" : "=r"(r) : "f"(x));
    return __uint_as_float(r);
}

__device__ __forceinline__ void mma8(float* d, const uint32_t* a,
                                     uint32_t b0, uint32_t b1) {
    asm volatile(
        "mma.sync.aligned.m16n8k8.row.col.f32.tf32.tf32.f32 "
        "{%0,%1,%2,%3}, {%4,%5,%6,%7}, {%8,%9}, {%0,%1,%2,%3};"
        : "+f"(d[0]), "+f"(d[1]), "+f"(d[2]), "+f"(d[3])
        : "r"(a[0]), "r"(a[1]), "r"(a[2]), "r"(a[3]), "r"(b0), "r"(b1));
}

#define CP_COMMIT() asm volatile("cp.async.commit_group;" ::: "memory")

__device__ __forceinline__ void cp16(uint32_t dst, const float* src) {
    asm volatile("cp.async.cg.shared.global [%0], [%1], 16;"
                 :: "r"(dst), "l"(src) : "memory");
}

// ---------------- init kernels ----------------
// pack codebook into mma B-fragment layout (tf32 hi/lo splits)
__global__ void vq_pack_kernel(const float* __restrict__ cb) {
    int t = blockIdx.x * blockDim.x + threadIdx.x;   // code*64 + k
    int code = t >> 6, k = t & 63;
    float v = cb[t];
    float h  = tf32_rna(v);
    float lo = tf32_rna(v - h);
    int T  = code >> 6;
    int nt = (code & 63) >> 3, cg = code & 7;
    int ks = k >> 3, w = k & 7;
    int e  = w >> 2, tt = w & 3;
    int l  = cg * 4 + tt;
    size_t base = (size_t)T * 8192 + (size_t)(ks * 8 + nt) * 64 + l * 2 + e;
    g_cbp[base]        = h;    // split 0 (hi)
    g_cbp[base + 4096] = lo;   // split 1 (lo), +64 chunks * 64
}

__global__ void vq_norm_kernel(const float* __restrict__ cb) {
    int k = blockIdx.x * blockDim.x + threadIdx.x;
    if (k == 0) g_accum = 0.0;
    if (k < KCODES) {
        const float4* r = reinterpret_cast<const float4*>(cb + (size_t)k * DK);
        float s = 0.f;
        #pragma unroll
        for (int u = 0; u < DK / 4; u++) {
            float4 v = r[u];
            s += v.x * v.x + v.y * v.y + v.z * v.z + v.w * v.w;
        }
        g_cn2[k] = 0.5f * s;
    }
}

__global__ void vq_finish_kernel(float* __restrict__ out, int NQ) {
    out[(size_t)NQ * (DK + 1)] = (float)(g_accum / ((double)NQ * (double)DK));
}

// ---------------- main kernel ----------------
// SMEM: B bufs 2*32768B @0, norms 2*256B @65536, bq 128 ints @66048, wred @66560
#define SMEM_TOTAL 66816

__device__ __forceinline__ void issue_tile(uint32_t sb, int T, int buf, int tid) {
    const float* src = g_cbp + (size_t)T * 8192;
    #pragma unroll
    for (int r = 0; r < 8; r++) {
        int i = r * THREADS + tid;                    // 16B unit index (0..2047)
        cp16(sb + buf * 32768u + (uint32_t)i * 16u, src + i * 4);
    }
    if (tid < 16) {
        cp16(sb + 65536u + buf * 256u + (uint32_t)tid * 16u,
             g_cn2 + T * NT + tid * 4);
    }
}

__global__ __launch_bounds__(THREADS, 1)
void vq_main_kernel(const float* __restrict__ z,
                    const float* __restrict__ cb,
                    float* __restrict__ out, int NQ) {
    extern __shared__ char smem[];
    float* Bsm  = reinterpret_cast<float*>(smem);
    float* Nsm  = reinterpret_cast<float*>(smem + 65536);
    int*   bq   = reinterpret_cast<int*>(smem + 66048);
    float* wred = reinterpret_cast<float*>(smem + 66560);
    const uint32_t sb = (uint32_t)__cvta_generic_to_shared(smem);

    const int tid  = threadIdx.x;
    const int warp = tid >> 5, lane = tid & 31;
    const int g    = lane >> 2, tq = lane & 3;
    const int q0   = blockIdx.x * MT;

    // ---- A fragments (z rows warp*16..+15), tf32 hi/lo, persistent in regs ----
    uint32_t ah[32], al[32];
    {
        const float* zb = z + (size_t)(q0 + warp * 16) * DK;
        #pragma unroll
        for (int ks = 0; ks < 8; ks++) {
            #pragma unroll
            for (int j = 0; j < 4; j++) {
                int row = g + (j & 1) * 8;
                int col = ks * 8 + tq + (j >> 1) * 4;
                float v = zb[row * DK + col];
                float h = tf32_rna(v);
                ah[ks * 4 + j] = __float_as_uint(h);
                al[ks * 4 + j] = __float_as_uint(tf32_rna(v - h));
            }
        }
    }

    issue_tile(sb, 0, 0, tid); CP_COMMIT();
    issue_tile(sb, 1, 1, tid); CP_COMMIT();

    float best0 = -3.4e38f, best1 = -3.4e38f;
    int   bi0 = 0, bi1 = 0;

    for (int T = 0; T < TILES; T++) {
        asm volatile("cp.async.wait_group 1;" ::: "memory");
        __syncthreads();

        float acc[8][4];
        #pragma unroll
        for (int nt = 0; nt < 8; nt++)
            acc[nt][0] = acc[nt][1] = acc[nt][2] = acc[nt][3] = 0.f;

        const float* bh = Bsm + (T & 1) * 8192;        // split 0
        const float* bl = bh + 4096;                   // split 1

        #pragma unroll
        for (int ks = 0; ks < 8; ks++) {
            #pragma unroll
            for (int nt = 0; nt < 8; nt++) {
                float2 b = *reinterpret_cast<const float2*>(bh + (ks * 8 + nt) * 64 + lane * 2);
                mma8(acc[nt], ah + ks * 4, __float_as_uint(b.x), __float_as_uint(b.y));
            }
        }
        #pragma unroll
        for (int ks = 0; ks < 8; ks++) {
            #pragma unroll
            for (int nt = 0; nt < 8; nt++) {
                float2 b = *reinterpret_cast<const float2*>(bl + (ks * 8 + nt) * 64 + lane * 2);
                mma8(acc[nt], ah + ks * 4, __float_as_uint(b.x), __float_as_uint(b.y));
            }
        }
        #pragma unroll
        for (int ks = 0; ks < 8; ks++) {
            #pragma unroll
            for (int nt = 0; nt < 8; nt++) {
                float2 b = *reinterpret_cast<const float2*>(bh + (ks * 8 + nt) * 64 + lane * 2);
                mma8(acc[nt], al + ks * 4, __float_as_uint(b.x), __float_as_uint(b.y));
            }
        }

        // ---- fused argmax (thread owns rows g, g+8 ; cols 2tq, 2tq+1 per n8) ----
        const float* nrm = Nsm + (T & 1) * NT;
        #pragma unroll
        for (int nt = 0; nt < 8; nt++) {
            float2 nn = *reinterpret_cast<const float2*>(nrm + nt * 8 + 2 * tq);
            int idx = T * NT + nt * 8 + 2 * tq;
            float s0 = acc[nt][0] - nn.x; if (s0 > best0) { best0 = s0; bi0 = idx; }
            float s1 = acc[nt][1] - nn.y; if (s1 > best0) { best0 = s1; bi0 = idx + 1; }
            float s2 = acc[nt][2] - nn.x; if (s2 > best1) { best1 = s2; bi1 = idx; }
            float s3 = acc[nt][3] - nn.y; if (s3 > best1) { best1 = s3; bi1 = idx + 1; }
        }

        __syncthreads();
        if (T + 2 < TILES) issue_tile(sb, T + 2, T & 1, tid);
        CP_COMMIT();
    }

    // ---- quad reduction (lanes sharing a row), tie -> lower index ----
    #pragma unroll
    for (int off = 1; off <= 2; off <<= 1) {
        float ob = __shfl_xor_sync(0xffffffffu, best0, off);
        int   oi = __shfl_xor_sync(0xffffffffu, bi0,   off);
        if (ob > best0 || (ob == best0 && oi < bi0)) { best0 = ob; bi0 = oi; }
        ob = __shfl_xor_sync(0xffffffffu, best1, off);
        oi = __shfl_xor_sync(0xffffffffu, bi1,   off);
        if (ob > best1 || (ob == best1 && oi < bi1)) { best1 = ob; bi1 = oi; }
    }
    if (tq == 0) {
        bq[warp * 16 + g]     = bi0;
        bq[warp * 16 + g + 8] = bi1;
    }
    __syncthreads();

    // ---- indices output (as float) ----
    if (tid < MT) out[(size_t)NQ * DK + q0 + tid] = (float)bq[tid];

    // ---- codes output + commit loss (thread: half a query row = 32 floats) ----
    float ls = 0.f;
    {
        int q = tid >> 1, h = tid & 1;
        const float4* crow = reinterpret_cast<const float4*>(cb + (size_t)bq[q] * DK) + h * 8;
        const float4* zrow = reinterpret_cast<const float4*>(z + (size_t)(q0 + q) * DK) + h * 8;
        float4*       orow = reinterpret_cast<float4*>(out + (size_t)(q0 + q) * DK) + h * 8;
        #pragma unroll
        for (int u = 0; u < 8; u++) {
            float4 c = crow[u], zz = zrow[u];
            orow[u] = c;
            float dx = c.x - zz.x, dy = c.y - zz.y, dz = c.z - zz.z, dw = c.w - zz.w;
            ls += dx * dx + dy * dy + dz * dz + dw * dw;
        }
    }
    #pragma unroll
    for (int off = 16; off >= 1; off >>= 1)
        ls += __shfl_down_sync(0xffffffffu, ls, off, 32);
    if ((tid & 31) == 0) wred[tid >> 5] = ls;
    __syncthreads();
    if (tid == 0) {
        float t = 0.f;
        #pragma unroll
        for (int w = 0; w < 8; w++) t += wred[w];
        atomicAdd(&g_accum, (double)t);
    }
}

extern "C" void kernel_launch(void* const* d_in, const int* in_sizes, int n_in,
                              void* d_out, int out_size) {
    (void)n_in; (void)out_size;
    const float* z  = (const float*)d_in[0];
    const float* cb = (const float*)d_in[1];
    float* out = (float*)d_out;

    const int NQ = in_sizes[0] / DK;   // 131072

    static int attr_set = 0;
    if (!attr_set) {
        cudaFuncSetAttribute(vq_main_kernel,
                             cudaFuncAttributeMaxDynamicSharedMemorySize, SMEM_TOTAL);
        attr_set = 1;
    }

    vq_pack_kernel<<<(KCODES * DK) / 256, 256>>>(cb);
    vq_norm_kernel<<<KCODES / 128, 128>>>(cb);
    vq_main_kernel<<<NQ / MT, THREADS, SMEM_TOTAL>>>(z, cb, out, NQ);
    vq_finish_kernel<<<1, 1>>>(out, NQ);
}

// round 8
// speedup vs baseline: 1.7329x; 1.1127x over previous
#include <cuda_runtime.h>
#include <cstdint>

// VQQuantizer via mma.sync tf32 3-MMA fp32 emulation (plain sm_103 target).
// z [131072 x 64] f32, codebook [2048 x 64] f32.
// out = [codes (N*64) | indices (N) | loss (1)] f32.
// score = z.c - 0.5||c||^2 ; argmax score == argmin dist.
//
// R4: B splits interleaved -> 1 LDS.128 feeds 3 MMAs; occupancy 2.

#define DK      64
#define MT      128          // queries per CTA
#define NT      64           // codes per tile
#define KCODES  2048
#define TILES   (KCODES / NT)
#define THREADS 256

// packed codebook: per tile [chunk=ks*8+nt (64)][lane(32)][{bh0,bh1,bl0,bl1}]
__device__ __align__(16) float g_cbp[KCODES * DK * 2];
__device__ __align__(16) float g_cn2[KCODES];
__device__ double g_accum;

// ---------------- helpers ----------------
__device__ __forceinline__ float tf32_rna(float x) {
    uint32_t r;
    asm("cvt.rna.tf32.f32 %0, %1;" : "=r"(r) : "f"(x));
    return __uint_as_float(r);
}

__device__ __forceinline__ void mma8(float* d, const uint32_t* a,
                                     float b0, float b1) {
    asm volatile(
        "mma.sync.aligned.m16n8k8.row.col.f32.tf32.tf32.f32 "
        "{%0,%1,%2,%3}, {%4,%5,%6,%7}, {%8,%9}, {%0,%1,%2,%3};"
        : "+f"(d[0]), "+f"(d[1]), "+f"(d[2]), "+f"(d[3])
        : "r"(a[0]), "r"(a[1]), "r"(a[2]), "r"(a[3]),
          "r"(__float_as_uint(b0)), "r"(__float_as_uint(b1)));
}

#define CP_COMMIT() asm volatile("cp.async.commit_group;" ::: "memory")

__device__ __forceinline__ void cp16(uint32_t dst, const float* src) {
    asm volatile("cp.async.cg.shared.global [%0], [%1], 16;"
                 :: "r"(dst), "l"(src) : "memory");
}

// ---------------- init kernels ----------------
// pack codebook into interleaved mma B-fragment layout (tf32 hi/lo)
__global__ void vq_pack_kernel(const float* __restrict__ cb) {
    int t = blockIdx.x * blockDim.x + threadIdx.x;   // code*64 + k
    int code = t >> 6, k = t & 63;
    float v = cb[t];
    float h  = tf32_rna(v);
    float lo = tf32_rna(v - h);
    int T  = code >> 6;
    int nt = (code & 63) >> 3, cg = code & 7;        // n-tile, n within 8
    int ks = k >> 3, w = k & 7;
    int e  = w >> 2, tt = w & 3;                     // b0/b1, k%4
    int l  = cg * 4 + tt;                            // lane
    size_t base = (size_t)T * 8192 + (size_t)(ks * 8 + nt) * 128 + l * 4;
    g_cbp[base + e]     = h;                         // bh
    g_cbp[base + 2 + e] = lo;                        // bl
}

__global__ void vq_norm_kernel(const float* __restrict__ cb) {
    int k = blockIdx.x * blockDim.x + threadIdx.x;
    if (k == 0) g_accum = 0.0;
    if (k < KCODES) {
        const float4* r = reinterpret_cast<const float4*>(cb + (size_t)k * DK);
        float s = 0.f;
        #pragma unroll
        for (int u = 0; u < DK / 4; u++) {
            float4 v = r[u];
            s += v.x * v.x + v.y * v.y + v.z * v.z + v.w * v.w;
        }
        g_cn2[k] = 0.5f * s;
    }
}

__global__ void vq_finish_kernel(float* __restrict__ out, int NQ) {
    out[(size_t)NQ * (DK + 1)] = (float)(g_accum / ((double)NQ * (double)DK));
}

// ---------------- main kernel ----------------
// SMEM: B bufs 2*32768B @0, norms 2*256B @65536, bq 128 ints @66048, wred @66560
#define SMEM_TOTAL 66816

__device__ __forceinline__ void issue_tile(uint32_t sb, int T, int buf, int tid) {
    const float* src = g_cbp + (size_t)T * 8192;
    #pragma unroll
    for (int r = 0; r < 8; r++) {
        int i = r * THREADS + tid;                    // 16B unit index (0..2047)
        cp16(sb + buf * 32768u + (uint32_t)i * 16u, src + i * 4);
    }
    if (tid < 16) {
        cp16(sb + 65536u + buf * 256u + (uint32_t)tid * 16u,
             g_cn2 + T * NT + tid * 4);
    }
}

__global__ __launch_bounds__(THREADS, 2)
void vq_main_kernel(const float* __restrict__ z,
                    const float* __restrict__ cb,
                    float* __restrict__ out, int NQ) {
    extern __shared__ char smem[];
    float* Bsm  = reinterpret_cast<float*>(smem);
    float* Nsm  = reinterpret_cast<float*>(smem + 65536);
    int*   bq   = reinterpret_cast<int*>(smem + 66048);
    float* wred = reinterpret_cast<float*>(smem + 66560);
    const uint32_t sb = (uint32_t)__cvta_generic_to_shared(smem);

    const int tid  = threadIdx.x;
    const int warp = tid >> 5, lane = tid & 31;
    const int g    = lane >> 2, tq = lane & 3;
    const int q0   = blockIdx.x * MT;

    // ---- A fragments (z rows warp*16..+15), tf32 hi/lo, persistent in regs ----
    uint32_t ah[32], al[32];
    {
        const float* zb = z + (size_t)(q0 + warp * 16) * DK;
        #pragma unroll
        for (int ks = 0; ks < 8; ks++) {
            #pragma unroll
            for (int j = 0; j < 4; j++) {
                int row = g + (j & 1) * 8;
                int col = ks * 8 + tq + (j >> 1) * 4;
                float v = zb[row * DK + col];
                float h = tf32_rna(v);
                ah[ks * 4 + j] = __float_as_uint(h);
                al[ks * 4 + j] = __float_as_uint(tf32_rna(v - h));
            }
        }
    }

    issue_tile(sb, 0, 0, tid); CP_COMMIT();
    issue_tile(sb, 1, 1, tid); CP_COMMIT();

    float best0 = -3.4e38f, best1 = -3.4e38f;
    int   bi0 = 0, bi1 = 0;

    for (int T = 0; T < TILES; T++) {
        asm volatile("cp.async.wait_group 1;" ::: "memory");
        __syncthreads();

        float acc[8][4];
        #pragma unroll
        for (int nt = 0; nt < 8; nt++)
            acc[nt][0] = acc[nt][1] = acc[nt][2] = acc[nt][3] = 0.f;

        const float* Bt = Bsm + (T & 1) * 8192 + lane * 4;

        #pragma unroll
        for (int ks = 0; ks < 8; ks++) {
            #pragma unroll
            for (int nt = 0; nt < 8; nt++) {
                float4 b = *reinterpret_cast<const float4*>(Bt + (ks * 8 + nt) * 128);
                mma8(acc[nt], ah + ks * 4, b.x, b.y);   // ah*bh
                mma8(acc[nt], ah + ks * 4, b.z, b.w);   // ah*bl
                mma8(acc[nt], al + ks * 4, b.x, b.y);   // al*bh
            }
        }

        // ---- fused argmax (thread owns rows g, g+8 ; cols 2tq, 2tq+1 per n8) ----
        const float* nrm = Nsm + (T & 1) * NT;
        #pragma unroll
        for (int nt = 0; nt < 8; nt++) {
            float2 nn = *reinterpret_cast<const float2*>(nrm + nt * 8 + 2 * tq);
            int idx = T * NT + nt * 8 + 2 * tq;
            float s0 = acc[nt][0] - nn.x; if (s0 > best0) { best0 = s0; bi0 = idx; }
            float s1 = acc[nt][1] - nn.y; if (s1 > best0) { best0 = s1; bi0 = idx + 1; }
            float s2 = acc[nt][2] - nn.x; if (s2 > best1) { best1 = s2; bi1 = idx; }
            float s3 = acc[nt][3] - nn.y; if (s3 > best1) { best1 = s3; bi1 = idx + 1; }
        }

        __syncthreads();
        if (T + 2 < TILES) issue_tile(sb, T + 2, T & 1, tid);
        CP_COMMIT();
    }

    // ---- quad reduction (lanes sharing a row), tie -> lower index ----
    #pragma unroll
    for (int off = 1; off <= 2; off <<= 1) {
        float ob = __shfl_xor_sync(0xffffffffu, best0, off);
        int   oi = __shfl_xor_sync(0xffffffffu, bi0,   off);
        if (ob > best0 || (ob == best0 && oi < bi0)) { best0 = ob; bi0 = oi; }
        ob = __shfl_xor_sync(0xffffffffu, best1, off);
        oi = __shfl_xor_sync(0xffffffffu, bi1,   off);
        if (ob > best1 || (ob == best1 && oi < bi1)) { best1 = ob; bi1 = oi; }
    }
    if (tq == 0) {
        bq[warp * 16 + g]     = bi0;
        bq[warp * 16 + g + 8] = bi1;
    }
    __syncthreads();

    // ---- indices output (as float) ----
    if (tid < MT) out[(size_t)NQ * DK + q0 + tid] = (float)bq[tid];

    // ---- codes output + commit loss (thread: half a query row = 32 floats) ----
    float ls = 0.f;
    {
        int q = tid >> 1, h = tid & 1;
        const float4* crow = reinterpret_cast<const float4*>(cb + (size_t)bq[q] * DK) + h * 8;
        const float4* zrow = reinterpret_cast<const float4*>(z + (size_t)(q0 + q) * DK) + h * 8;
        float4*       orow = reinterpret_cast<float4*>(out + (size_t)(q0 + q) * DK) + h * 8;
        #pragma unroll
        for (int u = 0; u < 8; u++) {
            float4 c = crow[u], zz = zrow[u];
            orow[u] = c;
            float dx = c.x - zz.x, dy = c.y - zz.y, dz = c.z - zz.z, dw = c.w - zz.w;
            ls += dx * dx + dy * dy + dz * dz + dw * dw;
        }
    }
    #pragma unroll
    for (int off = 16; off >= 1; off >>= 1)
        ls += __shfl_down_sync(0xffffffffu, ls, off, 32);
    if ((tid & 31) == 0) wred[tid >> 5] = ls;
    __syncthreads();
    if (tid == 0) {
        float t = 0.f;
        #pragma unroll
        for (int w = 0; w < 8; w++) t += wred[w];
        atomicAdd(&g_accum, (double)t);
    }
}

extern "C" void kernel_launch(void* const* d_in, const int* in_sizes, int n_in,
                              void* d_out, int out_size) {
    (void)n_in; (void)out_size;
    const float* z  = (const float*)d_in[0];
    const float* cb = (const float*)d_in[1];
    float* out = (float*)d_out;

    const int NQ = in_sizes[0] / DK;   // 131072

    static int attr_set = 0;
    if (!attr_set) {
        cudaFuncSetAttribute(vq_main_kernel,
                             cudaFuncAttributeMaxDynamicSharedMemorySize, SMEM_TOTAL);
        attr_set = 1;
    }

    vq_pack_kernel<<<(KCODES * DK) / 256, 256>>>(cb);
    vq_norm_kernel<<<KCODES / 128, 128>>>(cb);
    vq_main_kernel<<<NQ / MT, THREADS, SMEM_TOTAL>>>(z, cb, out, NQ);
    vq_finish_kernel<<<1, 1>>>(out, NQ);
}

// round 9
// speedup vs baseline: 1.7351x; 1.0012x over previous
#include <cuda_runtime.h>
#include <cstdint>

// VQQuantizer via mma.sync tf32 3-MMA fp32 emulation (plain sm_103 target).
// z [131072 x 64] f32, codebook [2048 x 64] f32.
// out = [codes (N*64) | indices (N) | loss (1)] f32.
// score = z.c - 0.5||c||^2 ; argmax score == argmin dist.
//
// R5: nt split into two half-passes (acc 32->16 regs, kill spills at occ 2);
//     1-deep register prefetch of B chunks.

#define DK      64
#define MT      128          // queries per CTA
#define NT      64           // codes per tile
#define KCODES  2048
#define TILES   (KCODES / NT)
#define THREADS 256

// packed codebook: per tile [chunk=ks*8+nt (64)][lane(32)][{bh0,bh1,bl0,bl1}]
__device__ __align__(16) float g_cbp[KCODES * DK * 2];
__device__ __align__(16) float g_cn2[KCODES];
__device__ double g_accum;

// ---------------- helpers ----------------
__device__ __forceinline__ float tf32_rna(float x) {
    uint32_t r;
    asm("cvt.rna.tf32.f32 %0, %1;" : "=r"(r) : "f"(x));
    return __uint_as_float(r);
}

__device__ __forceinline__ void mma8(float* d, const uint32_t* a,
                                     float b0, float b1) {
    asm volatile(
        "mma.sync.aligned.m16n8k8.row.col.f32.tf32.tf32.f32 "
        "{%0,%1,%2,%3}, {%4,%5,%6,%7}, {%8,%9}, {%0,%1,%2,%3};"
        : "+f"(d[0]), "+f"(d[1]), "+f"(d[2]), "+f"(d[3])
        : "r"(a[0]), "r"(a[1]), "r"(a[2]), "r"(a[3]),
          "r"(__float_as_uint(b0)), "r"(__float_as_uint(b1)));
}

#define CP_COMMIT() asm volatile("cp.async.commit_group;" ::: "memory")

__device__ __forceinline__ void cp16(uint32_t dst, const float* src) {
    asm volatile("cp.async.cg.shared.global [%0], [%1], 16;"
                 :: "r"(dst), "l"(src) : "memory");
}

// ---------------- init kernels ----------------
// pack codebook into interleaved mma B-fragment layout (tf32 hi/lo)
__global__ void vq_pack_kernel(const float* __restrict__ cb) {
    int t = blockIdx.x * blockDim.x + threadIdx.x;   // code*64 + k
    int code = t >> 6, k = t & 63;
    float v = cb[t];
    float h  = tf32_rna(v);
    float lo = tf32_rna(v - h);
    int T  = code >> 6;
    int nt = (code & 63) >> 3, cg = code & 7;        // n-tile, n within 8
    int ks = k >> 3, w = k & 7;
    int e  = w >> 2, tt = w & 3;                     // b0/b1, k%4
    int l  = cg * 4 + tt;                            // lane
    size_t base = (size_t)T * 8192 + (size_t)(ks * 8 + nt) * 128 + l * 4;
    g_cbp[base + e]     = h;                         // bh
    g_cbp[base + 2 + e] = lo;                        // bl
}

__global__ void vq_norm_kernel(const float* __restrict__ cb) {
    int k = blockIdx.x * blockDim.x + threadIdx.x;
    if (k == 0) g_accum = 0.0;
    if (k < KCODES) {
        const float4* r = reinterpret_cast<const float4*>(cb + (size_t)k * DK);
        float s = 0.f;
        #pragma unroll
        for (int u = 0; u < DK / 4; u++) {
            float4 v = r[u];
            s += v.x * v.x + v.y * v.y + v.z * v.z + v.w * v.w;
        }
        g_cn2[k] = 0.5f * s;
    }
}

__global__ void vq_finish_kernel(float* __restrict__ out, int NQ) {
    out[(size_t)NQ * (DK + 1)] = (float)(g_accum / ((double)NQ * (double)DK));
}

// ---------------- main kernel ----------------
// SMEM: B bufs 2*32768B @0, norms 2*256B @65536, bq 128 ints @66048, wred @66560
#define SMEM_TOTAL 66816

__device__ __forceinline__ void issue_tile(uint32_t sb, int T, int buf, int tid) {
    const float* src = g_cbp + (size_t)T * 8192;
    #pragma unroll
    for (int r = 0; r < 8; r++) {
        int i = r * THREADS + tid;                    // 16B unit index (0..2047)
        cp16(sb + buf * 32768u + (uint32_t)i * 16u, src + i * 4);
    }
    if (tid < 16) {
        cp16(sb + 65536u + buf * 256u + (uint32_t)tid * 16u,
             g_cn2 + T * NT + tid * 4);
    }
}

__global__ __launch_bounds__(THREADS, 2)
void vq_main_kernel(const float* __restrict__ z,
                    const float* __restrict__ cb,
                    float* __restrict__ out, int NQ) {
    extern __shared__ char smem[];
    float* Bsm  = reinterpret_cast<float*>(smem);
    float* Nsm  = reinterpret_cast<float*>(smem + 65536);
    int*   bq   = reinterpret_cast<int*>(smem + 66048);
    float* wred = reinterpret_cast<float*>(smem + 66560);
    const uint32_t sb = (uint32_t)__cvta_generic_to_shared(smem);

    const int tid  = threadIdx.x;
    const int warp = tid >> 5, lane = tid & 31;
    const int g    = lane >> 2, tq = lane & 3;
    const int q0   = blockIdx.x * MT;

    // ---- A fragments (z rows warp*16..+15), tf32 hi/lo, persistent in regs ----
    uint32_t ah[32], al[32];
    {
        const float* zb = z + (size_t)(q0 + warp * 16) * DK;
        #pragma unroll
        for (int ks = 0; ks < 8; ks++) {
            #pragma unroll
            for (int j = 0; j < 4; j++) {
                int row = g + (j & 1) * 8;
                int col = ks * 8 + tq + (j >> 1) * 4;
                float v = zb[row * DK + col];
                float h = tf32_rna(v);
                ah[ks * 4 + j] = __float_as_uint(h);
                al[ks * 4 + j] = __float_as_uint(tf32_rna(v - h));
            }
        }
    }

    issue_tile(sb, 0, 0, tid); CP_COMMIT();
    issue_tile(sb, 1, 1, tid); CP_COMMIT();

    float best0 = -3.4e38f, best1 = -3.4e38f;
    int   bi0 = 0, bi1 = 0;

    for (int T = 0; T < TILES; T++) {
        asm volatile("cp.async.wait_group 1;" ::: "memory");
        __syncthreads();

        const float* nrmT = Nsm + (T & 1) * NT;

        #pragma unroll
        for (int half = 0; half < 2; half++) {
            float acc[4][4];
            #pragma unroll
            for (int j = 0; j < 4; j++)
                acc[j][0] = acc[j][1] = acc[j][2] = acc[j][3] = 0.f;

            // chunks for this half: index ks*8 + (half*4 + j)
            const float* Bp = Bsm + (T & 1) * 8192 + (half * 4) * 128 + lane * 4;

            float4 bcur = *reinterpret_cast<const float4*>(Bp);   // ks=0, j=0
            #pragma unroll
            for (int ks = 0; ks < 8; ks++) {
                #pragma unroll
                for (int j = 0; j < 4; j++) {
                    float4 b = bcur;
                    if (!(ks == 7 && j == 3)) {
                        int nj = (j + 1) & 3;
                        int nk = ks + ((j + 1) >> 2);
                        bcur = *reinterpret_cast<const float4*>(Bp + (nk * 8 + nj) * 128);
                    }
                    mma8(acc[j], ah + ks * 4, b.x, b.y);   // ah*bh
                    mma8(acc[j], ah + ks * 4, b.z, b.w);   // ah*bl
                    mma8(acc[j], al + ks * 4, b.x, b.y);   // al*bh
                }
            }

            // ---- fused argmax for nt = half*4 + j ----
            #pragma unroll
            for (int j = 0; j < 4; j++) {
                int ntg = half * 4 + j;
                float2 nn = *reinterpret_cast<const float2*>(nrmT + ntg * 8 + 2 * tq);
                int idx = T * NT + ntg * 8 + 2 * tq;
                float s0 = acc[j][0] - nn.x; if (s0 > best0) { best0 = s0; bi0 = idx; }
                float s1 = acc[j][1] - nn.y; if (s1 > best0) { best0 = s1; bi0 = idx + 1; }
                float s2 = acc[j][2] - nn.x; if (s2 > best1) { best1 = s2; bi1 = idx; }
                float s3 = acc[j][3] - nn.y; if (s3 > best1) { best1 = s3; bi1 = idx + 1; }
            }
        }

        __syncthreads();
        if (T + 2 < TILES) issue_tile(sb, T + 2, T & 1, tid);
        CP_COMMIT();
    }

    // ---- quad reduction (lanes sharing a row), tie -> lower index ----
    #pragma unroll
    for (int off = 1; off <= 2; off <<= 1) {
        float ob = __shfl_xor_sync(0xffffffffu, best0, off);
        int   oi = __shfl_xor_sync(0xffffffffu, bi0,   off);
        if (ob > best0 || (ob == best0 && oi < bi0)) { best0 = ob; bi0 = oi; }
        ob = __shfl_xor_sync(0xffffffffu, best1, off);
        oi = __shfl_xor_sync(0xffffffffu, bi1,   off);
        if (ob > best1 || (ob == best1 && oi < bi1)) { best1 = ob; bi1 = oi; }
    }
    if (tq == 0) {
        bq[warp * 16 + g]     = bi0;
        bq[warp * 16 + g + 8] = bi1;
    }
    __syncthreads();

    // ---- indices output (as float) ----
    if (tid < MT) out[(size_t)NQ * DK + q0 + tid] = (float)bq[tid];

    // ---- codes output + commit loss (thread: half a query row = 32 floats) ----
    float ls = 0.f;
    {
        int q = tid >> 1, h = tid & 1;
        const float4* crow = reinterpret_cast<const float4*>(cb + (size_t)bq[q] * DK) + h * 8;
        const float4* zrow = reinterpret_cast<const float4*>(z + (size_t)(q0 + q) * DK) + h * 8;
        float4*       orow = reinterpret_cast<float4*>(out + (size_t)(q0 + q) * DK) + h * 8;
        #pragma unroll
        for (int u = 0; u < 8; u++) {
            float4 c = crow[u], zz = zrow[u];
            orow[u] = c;
            float dx = c.x - zz.x, dy = c.y - zz.y, dz = c.z - zz.z, dw = c.w - zz.w;
            ls += dx * dx + dy * dy + dz * dz + dw * dw;
        }
    }
    #pragma unroll
    for (int off = 16; off >= 1; off >>= 1)
        ls += __shfl_down_sync(0xffffffffu, ls, off, 32);
    if ((tid & 31) == 0) wred[tid >> 5] = ls;
    __syncthreads();
    if (tid == 0) {
        float t = 0.f;
        #pragma unroll
        for (int w = 0; w < 8; w++) t += wred[w];
        atomicAdd(&g_accum, (double)t);
    }
}

extern "C" void kernel_launch(void* const* d_in, const int* in_sizes, int n_in,
                              void* d_out, int out_size) {
    (void)n_in; (void)out_size;
    const float* z  = (const float*)d_in[0];
    const float* cb = (const float*)d_in[1];
    float* out = (float*)d_out;

    const int NQ = in_sizes[0] / DK;   // 131072

    static int attr_set = 0;
    if (!attr_set) {
        cudaFuncSetAttribute(vq_main_kernel,
                             cudaFuncAttributeMaxDynamicSharedMemorySize, SMEM_TOTAL);
        attr_set = 1;
    }

    vq_pack_kernel<<<(KCODES * DK) / 256, 256>>>(cb);
    vq_norm_kernel<<<KCODES / 128, 128>>>(cb);
    vq_main_kernel<<<NQ / MT, THREADS, SMEM_TOTAL>>>(z, cb, out, NQ);
    vq_finish_kernel<<<1, 1>>>(out, NQ);
}